// round 5
// baseline (speedup 1.0000x reference)
#include <cuda_runtime.h>

#define BB 16
#define NP 4000
#define TK 1024           // sorted candidate capacity (pow2)
#define KSEL 512          // target top-K for threshold selection
#define DD 1024
#define NROWS (BB*NP)
#define CLIPV 4.135166556742356f   // log(1000/16)
#define FULLM 0xffffffffu

__device__ float g_scores[NROWS];
__device__ unsigned long long g_keys[BB * TK];

// ---------------------------------------------------------------------------
// Kernel 1: fused head. DRAM-bound (262 MB feats streamed once).
// 512 threads = 16 warps x 4 rows. Writes boxes + zeroed score slot.
// ---------------------------------------------------------------------------
__global__ __launch_bounds__(512) void head_kernel(
    const float* __restrict__ feats, const float* __restrict__ proposals,
    const float* __restrict__ W_cls, const float* __restrict__ b_cls,
    const float* __restrict__ W_box, const float* __restrict__ b_box,
    float* __restrict__ out)
{
    __shared__ float4 wS[6 * 256];   // 6 rows x 1024 floats = 24 KB
    const int tid = threadIdx.x;

    for (int i = tid; i < 6 * 256; i += 512) {
        int c = i >> 8, e = i & 255;
        const float* src = (c < 2) ? (W_cls + c * DD) : (W_box + (c + 2) * DD);
        wS[i] = reinterpret_cast<const float4*>(src)[e];
    }
    __syncthreads();

    const int warp = blockIdx.x * 16 + (tid >> 5);
    const int lane = tid & 31;
    const int row0 = warp * 4;
    if (row0 >= NROWS) return;

    float acc[4][6];
    #pragma unroll
    for (int r = 0; r < 4; r++)
        #pragma unroll
        for (int c = 0; c < 6; c++) acc[r][c] = 0.f;

    const float4* f4 = reinterpret_cast<const float4*>(feats);

    #pragma unroll
    for (int j = 0; j < 8; j++) {
        const int off = lane + 32 * j;
        float4 fr[4];
        #pragma unroll
        for (int r = 0; r < 4; r++)
            fr[r] = __ldcs(&f4[(row0 + r) * 256 + off]);   // streaming load
        #pragma unroll
        for (int c = 0; c < 6; c++) {
            float4 w = wS[c * 256 + off];
            #pragma unroll
            for (int r = 0; r < 4; r++)
                acc[r][c] += fr[r].x * w.x + fr[r].y * w.y +
                             fr[r].z * w.z + fr[r].w * w.w;
        }
    }

    #pragma unroll
    for (int r = 0; r < 4; r++)
        #pragma unroll
        for (int c = 0; c < 6; c++)
            #pragma unroll
            for (int s = 16; s > 0; s >>= 1)
                acc[r][c] += __shfl_xor_sync(FULLM, acc[r][c], s);

    if (lane < 4) {
        float v0 = 0.f, v1 = 0.f, v2 = 0.f, v3 = 0.f, v4 = 0.f, v5 = 0.f;
        #pragma unroll
        for (int r = 0; r < 4; r++)
            if (lane == r) {
                v0 = acc[r][0]; v1 = acc[r][1]; v2 = acc[r][2];
                v3 = acc[r][3]; v4 = acc[r][4]; v5 = acc[r][5];
            }
        const int row = row0 + lane;

        float l0 = v0 + b_cls[0];
        float l1 = v1 + b_cls[1];
        float score = 1.f / (1.f + expf(l0 - l1));

        float dx = (v2 + b_box[4]) / 10.0f;
        float dy = (v3 + b_box[5]) / 10.0f;
        float dw = fminf((v4 + b_box[6]) / 5.0f, CLIPV);
        float dh = fminf((v5 + b_box[7]) / 5.0f, CLIPV);

        float4 p = reinterpret_cast<const float4*>(proposals)[row];
        float w  = p.z - p.x;
        float h  = p.w - p.y;
        float cx = p.x + 0.5f * w;
        float cy = p.y + 0.5f * h;
        float pcx = dx * w + cx;
        float pcy = dy * h + cy;
        float pw  = expf(dw) * w;
        float ph  = expf(dh) * h;

        float x1 = fminf(fmaxf(pcx - 0.5f * pw, 0.f), 800.f);
        float y1 = fminf(fmaxf(pcy - 0.5f * ph, 0.f), 800.f);
        float x2 = fminf(fmaxf(pcx + 0.5f * pw, 0.f), 800.f);
        float y2 = fminf(fmaxf(pcy + 0.5f * ph, 0.f), 800.f);

        float* o = out + (size_t)row * 5;
        o[0] = x1; o[1] = y1; o[2] = x2; o[3] = y2;
        o[4] = 0.f;                       // default: not kept
        g_scores[row] = (score > 0.25f) ? score : 0.f;
    }
}

// ---------------------------------------------------------------------------
// Kernel 2: per-batch candidate selection + bitonic sort of top-C keys.
// ---------------------------------------------------------------------------
__global__ __launch_bounds__(1024) void prep_kernel()
{
    __shared__ unsigned long long KEY[TK];
    __shared__ int hist[256];
    __shared__ unsigned tbits_s;
    __shared__ int ccount;

    const int b = blockIdx.x;
    const int t = threadIdx.x;
    const float* gs = g_scores + b * NP;

    if (t < 256) hist[t] = 0;
    if (t == 0) { ccount = 0; tbits_s = 0x3E800000u; }
    __syncthreads();

    // histogram of positive score bits
    for (int n = t; n < NP; n += 1024) {
        float s = gs[n];
        if (s > 0.f) {
            unsigned bits = __float_as_uint(s);   // in (0x3E800000, 0x3F800000]
            int bin = min(max((int)((bits - 0x3E800000u) >> 16), 0), 255);
            atomicAdd(&hist[bin], 1);
        }
    }
    __syncthreads();

    // parallel suffix sums over 256 bins (Hillis-Steele)
    for (int off = 1; off < 256; off <<= 1) {
        int v = 0;
        if (t < 256) v = hist[t] + ((t + off < 256) ? hist[t + off] : 0);
        __syncthreads();
        if (t < 256) hist[t] = v;
        __syncthreads();
    }
    // largest bin index whose suffix count >= KSEL
    if (t < 256) {
        bool ok  = hist[t] >= KSEL;
        bool nxt = (t == 255) ? false : (hist[t + 1] >= KSEL);
        if (ok && !nxt) tbits_s = 0x3E800000u + ((unsigned)t << 16);
    }
    __syncthreads();
    const unsigned tbits = tbits_s;

    // compact candidates
    for (int n = t; n < NP; n += 1024) {
        float s = gs[n];
        if (s > 0.f) {
            unsigned bits = __float_as_uint(s);
            if (bits >= tbits) {
                int slot = atomicAdd(&ccount, 1);
                if (slot < TK)
                    KEY[slot] = ((unsigned long long)bits << 32)
                              | (unsigned long long)(4095 - n);
            }
        }
    }
    __syncthreads();
    const int C = min(ccount, TK);
    if (t >= C) KEY[t] = 0ull;
    __syncthreads();

    // bitonic sort descending, 1024 keys
    {
        unsigned long long e = KEY[t];
        #pragma unroll
        for (int k = 2; k <= 32; k <<= 1)
            #pragma unroll
            for (int j = k >> 1; j > 0; j >>= 1) {
                unsigned long long p = __shfl_xor_sync(FULLM, e, j);
                bool mx = ((t & k) == 0) == ((t & j) == 0);
                e = mx ? (e > p ? e : p) : (e < p ? e : p);
            }
        KEY[t] = e;
    }
    __syncthreads();

    for (int k = 64; k <= TK; k <<= 1) {
        for (int j = k >> 1; j >= 32; j >>= 1) {
            int ixj = t ^ j;
            if (ixj > t) {
                unsigned long long a = KEY[t];
                unsigned long long c = KEY[ixj];
                bool swap = ((t & k) == 0) ? (a < c) : (a > c);
                if (swap) { KEY[t] = c; KEY[ixj] = a; }
            }
            __syncthreads();
        }
        {
            unsigned long long e = KEY[t];
            bool dir = ((t & k) == 0);
            #pragma unroll
            for (int j = 16; j > 0; j >>= 1) {
                unsigned long long p = __shfl_xor_sync(FULLM, e, j);
                bool mx = dir == ((t & j) == 0);
                e = mx ? (e > p ? e : p) : (e < p ? e : p);
            }
            KEY[t] = e;
        }
        __syncthreads();
    }

    g_keys[b * TK + t] = KEY[t];
}

// ---------------------------------------------------------------------------
// Kernel 3: greedy walk, one warp per batch; writes kept scores directly.
// ---------------------------------------------------------------------------
__global__ __launch_bounds__(32) void walk_kernel(float* __restrict__ out)
{
    __shared__ float aX1[100], aY1[100], aX2[100], aY2[100], aAR[100];

    const int b = blockIdx.x;
    const int lane = threadIdx.x;
    const unsigned long long* keys = g_keys + b * TK;
    float* ob = out + (size_t)b * NP * 5;

    int npick = 0;
    for (int base = 0; base < TK && npick < 100; base += 32) {
        unsigned long long key = keys[base + lane];
        float sc = __uint_as_float((unsigned)(key >> 32));
        int   idx = 4095 - (int)(key & 0xFFFull);
        if (__shfl_sync(FULLM, sc, 0) <= 0.f) break;
        bool alive = sc > 0.f;

        float bx1 = 0.f, by1 = 0.f, bx2 = 0.f, by2 = 0.f, ba = 0.f;
        if (alive) {
            bx1 = __ldg(&ob[idx * 5 + 0]); by1 = __ldg(&ob[idx * 5 + 1]);
            bx2 = __ldg(&ob[idx * 5 + 2]); by2 = __ldg(&ob[idx * 5 + 3]);
            ba  = fmaxf(bx2 - bx1, 0.f) * fmaxf(by2 - by1, 0.f);
        }

        // test against previously accepted boxes (lane-parallel)
        for (int a = 0; a < npick; a++) {
            float ix1 = fmaxf(aX1[a], bx1);
            float iy1 = fmaxf(aY1[a], by1);
            float ix2 = fminf(aX2[a], bx2);
            float iy2 = fminf(aY2[a], by2);
            float inter = fmaxf(ix2 - ix1, 0.f) * fmaxf(iy2 - iy1, 0.f);
            float iou = inter / (aAR[a] + ba - inter + 1e-9f);
            if (iou > 0.5f) alive = false;
        }

        // intra-chunk pairwise conflicts: conf bit j = "I conflict with lane j"
        unsigned conf = 0;
        #pragma unroll 4
        for (int j = 0; j < 32; j++) {
            float cx1 = __shfl_sync(FULLM, bx1, j);
            float cy1 = __shfl_sync(FULLM, by1, j);
            float cx2 = __shfl_sync(FULLM, bx2, j);
            float cy2 = __shfl_sync(FULLM, by2, j);
            float ca  = __shfl_sync(FULLM, ba,  j);
            float ix1 = fmaxf(cx1, bx1);
            float iy1 = fmaxf(cy1, by1);
            float ix2 = fminf(cx2, bx2);
            float iy2 = fminf(cy2, by2);
            float inter = fmaxf(ix2 - ix1, 0.f) * fmaxf(iy2 - iy1, 0.f);
            float iou = inter / (ca + ba - inter + 1e-9f);
            if (iou > 0.5f) conf |= (1u << j);
        }
        // mycol (on lane k) = mask of lanes that conflict with k
        unsigned mycol = 0;
        #pragma unroll
        for (int j = 0; j < 32; j++) {
            unsigned bcol = __ballot_sync(FULLM, (conf >> j) & 1u);
            if (lane == j) mycol = bcol;
        }

        // scalar resolve, uniform across lanes (no local-mem indexing)
        unsigned alive_mask = __ballot_sync(FULLM, alive);
        unsigned picked = 0;
        const int np0 = npick;
        #pragma unroll 1
        for (int kk = 0; kk < 32; kk++) {
            unsigned kills = __shfl_sync(FULLM, mycol, kk);
            if ((alive_mask >> kk) & 1u) {
                picked |= 1u << kk;
                npick++;
                alive_mask &= ~(kills & (0xFFFFFFFEu << kk));
                if (npick >= 100) break;
            }
        }

        // append accepted boxes + write final score (parallel, popc rank)
        if ((picked >> lane) & 1u) {
            int pos = np0 + __popc(picked & ((1u << lane) - 1u));
            aX1[pos] = bx1; aY1[pos] = by1;
            aX2[pos] = bx2; aY2[pos] = by2;
            aAR[pos] = ba;
            ob[idx * 5 + 4] = sc;
        }
        __syncwarp(FULLM);
    }
}

extern "C" void kernel_launch(void* const* d_in, const int* in_sizes, int n_in,
                              void* d_out, int out_size)
{
    const float* feats     = (const float*)d_in[0];
    const float* proposals = (const float*)d_in[1];
    const float* W_cls     = (const float*)d_in[2];
    const float* b_cls     = (const float*)d_in[3];
    const float* W_box     = (const float*)d_in[4];
    const float* b_box     = (const float*)d_in[5];
    float* out = (float*)d_out;

    head_kernel<<<NROWS / 64, 512>>>(feats, proposals, W_cls, b_cls,
                                     W_box, b_box, out);
    prep_kernel<<<BB, 1024>>>();
    walk_kernel<<<BB, 32>>>(out);
}

// round 6
// speedup vs baseline: 1.0864x; 1.0864x over previous
#include <cuda_runtime.h>

#define BB 16
#define NP 4000
#define TK 1024           // sorted candidate capacity (pow2)
#define KSEL 512          // target top-K for threshold selection
#define DD 1024
#define NROWS (BB*NP)
#define CLIPV 4.135166556742356f   // log(1000/16)
#define FULLM 0xffffffffu

__device__ float g_scores[NROWS];
__device__ unsigned long long g_keys[BB * TK];

// ---------------------------------------------------------------------------
// Kernel 1: fused head. DRAM-bound (262 MB feats streamed once).
// 256 threads, 8 warps x 4 rows. Reg-capped for 32 warps/SM residency.
// ---------------------------------------------------------------------------
__global__ __launch_bounds__(256, 4) void head_kernel(
    const float* __restrict__ feats, const float* __restrict__ proposals,
    const float* __restrict__ W_cls, const float* __restrict__ b_cls,
    const float* __restrict__ W_box, const float* __restrict__ b_box,
    float* __restrict__ out)
{
    __shared__ float4 wS[6 * 256];   // 6 rows x 1024 floats = 24 KB
    const int tid = threadIdx.x;

    for (int i = tid; i < 6 * 256; i += 256) {
        int c = i >> 8, e = i & 255;
        const float* src = (c < 2) ? (W_cls + c * DD) : (W_box + (c + 2) * DD);
        wS[i] = reinterpret_cast<const float4*>(src)[e];
    }
    __syncthreads();

    const int warp = blockIdx.x * 8 + (tid >> 5);
    const int lane = tid & 31;
    const int row0 = warp * 4;
    if (row0 >= NROWS) return;

    float acc[4][6];
    #pragma unroll
    for (int r = 0; r < 4; r++)
        #pragma unroll
        for (int c = 0; c < 6; c++) acc[r][c] = 0.f;

    const float4* f4 = reinterpret_cast<const float4*>(feats);

    #pragma unroll
    for (int j = 0; j < 8; j++) {
        const int off = lane + 32 * j;
        float4 fr[4];
        #pragma unroll
        for (int r = 0; r < 4; r++)
            fr[r] = __ldcs(&f4[(row0 + r) * 256 + off]);   // streaming load
        #pragma unroll
        for (int c = 0; c < 6; c++) {
            float4 w = wS[c * 256 + off];
            #pragma unroll
            for (int r = 0; r < 4; r++)
                acc[r][c] += fr[r].x * w.x + fr[r].y * w.y +
                             fr[r].z * w.z + fr[r].w * w.w;
        }
    }

    #pragma unroll
    for (int r = 0; r < 4; r++)
        #pragma unroll
        for (int c = 0; c < 6; c++)
            #pragma unroll
            for (int s = 16; s > 0; s >>= 1)
                acc[r][c] += __shfl_xor_sync(FULLM, acc[r][c], s);

    if (lane < 4) {
        float v0 = 0.f, v1 = 0.f, v2 = 0.f, v3 = 0.f, v4 = 0.f, v5 = 0.f;
        #pragma unroll
        for (int r = 0; r < 4; r++)
            if (lane == r) {
                v0 = acc[r][0]; v1 = acc[r][1]; v2 = acc[r][2];
                v3 = acc[r][3]; v4 = acc[r][4]; v5 = acc[r][5];
            }
        const int row = row0 + lane;

        float l0 = v0 + b_cls[0];
        float l1 = v1 + b_cls[1];
        float score = 1.f / (1.f + expf(l0 - l1));

        float dx = (v2 + b_box[4]) / 10.0f;
        float dy = (v3 + b_box[5]) / 10.0f;
        float dw = fminf((v4 + b_box[6]) / 5.0f, CLIPV);
        float dh = fminf((v5 + b_box[7]) / 5.0f, CLIPV);

        float4 p = reinterpret_cast<const float4*>(proposals)[row];
        float w  = p.z - p.x;
        float h  = p.w - p.y;
        float cx = p.x + 0.5f * w;
        float cy = p.y + 0.5f * h;
        float pcx = dx * w + cx;
        float pcy = dy * h + cy;
        float pw  = expf(dw) * w;
        float ph  = expf(dh) * h;

        float x1 = fminf(fmaxf(pcx - 0.5f * pw, 0.f), 800.f);
        float y1 = fminf(fmaxf(pcy - 0.5f * ph, 0.f), 800.f);
        float x2 = fminf(fmaxf(pcx + 0.5f * pw, 0.f), 800.f);
        float y2 = fminf(fmaxf(pcy + 0.5f * ph, 0.f), 800.f);

        float* o = out + (size_t)row * 5;
        o[0] = x1; o[1] = y1; o[2] = x2; o[3] = y2;
        o[4] = 0.f;                       // default: not kept
        g_scores[row] = (score > 0.25f) ? score : 0.f;
    }
}

// ---------------------------------------------------------------------------
// Kernel 2: per-batch candidate selection + bitonic sort of top-C keys.
// ---------------------------------------------------------------------------
__global__ __launch_bounds__(1024) void prep_kernel()
{
    __shared__ unsigned long long KEY[TK];
    __shared__ int hist[256];
    __shared__ unsigned tbits_s;
    __shared__ int ccount;

    const int b = blockIdx.x;
    const int t = threadIdx.x;
    const float* gs = g_scores + b * NP;

    if (t < 256) hist[t] = 0;
    if (t == 0) { ccount = 0; tbits_s = 0x3E800000u; }
    __syncthreads();

    // histogram of positive score bits
    for (int n = t; n < NP; n += 1024) {
        float s = gs[n];
        if (s > 0.f) {
            unsigned bits = __float_as_uint(s);   // in (0x3E800000, 0x3F800000]
            int bin = min(max((int)((bits - 0x3E800000u) >> 16), 0), 255);
            atomicAdd(&hist[bin], 1);
        }
    }
    __syncthreads();

    // parallel suffix sums over 256 bins (Hillis-Steele)
    for (int off = 1; off < 256; off <<= 1) {
        int v = 0;
        if (t < 256) v = hist[t] + ((t + off < 256) ? hist[t + off] : 0);
        __syncthreads();
        if (t < 256) hist[t] = v;
        __syncthreads();
    }
    // largest bin index whose suffix count >= KSEL
    if (t < 256) {
        bool ok  = hist[t] >= KSEL;
        bool nxt = (t == 255) ? false : (hist[t + 1] >= KSEL);
        if (ok && !nxt) tbits_s = 0x3E800000u + ((unsigned)t << 16);
    }
    __syncthreads();
    const unsigned tbits = tbits_s;

    // compact candidates
    for (int n = t; n < NP; n += 1024) {
        float s = gs[n];
        if (s > 0.f) {
            unsigned bits = __float_as_uint(s);
            if (bits >= tbits) {
                int slot = atomicAdd(&ccount, 1);
                if (slot < TK)
                    KEY[slot] = ((unsigned long long)bits << 32)
                              | (unsigned long long)(4095 - n);
            }
        }
    }
    __syncthreads();
    const int C = min(ccount, TK);
    if (t >= C) KEY[t] = 0ull;
    __syncthreads();

    // bitonic sort descending, 1024 keys
    {
        unsigned long long e = KEY[t];
        #pragma unroll
        for (int k = 2; k <= 32; k <<= 1)
            #pragma unroll
            for (int j = k >> 1; j > 0; j >>= 1) {
                unsigned long long p = __shfl_xor_sync(FULLM, e, j);
                bool mx = ((t & k) == 0) == ((t & j) == 0);
                e = mx ? (e > p ? e : p) : (e < p ? e : p);
            }
        KEY[t] = e;
    }
    __syncthreads();

    for (int k = 64; k <= TK; k <<= 1) {
        for (int j = k >> 1; j >= 32; j >>= 1) {
            int ixj = t ^ j;
            if (ixj > t) {
                unsigned long long a = KEY[t];
                unsigned long long c = KEY[ixj];
                bool swap = ((t & k) == 0) ? (a < c) : (a > c);
                if (swap) { KEY[t] = c; KEY[ixj] = a; }
            }
            __syncthreads();
        }
        {
            unsigned long long e = KEY[t];
            bool dir = ((t & k) == 0);
            #pragma unroll
            for (int j = 16; j > 0; j >>= 1) {
                unsigned long long p = __shfl_xor_sync(FULLM, e, j);
                bool mx = dir == ((t & j) == 0);
                e = mx ? (e > p ? e : p) : (e < p ? e : p);
            }
            KEY[t] = e;
        }
        __syncthreads();
    }

    g_keys[b * TK + t] = KEY[t];
}

// ---------------------------------------------------------------------------
// Kernel 3: greedy walk, one warp per batch; writes kept scores directly.
// ---------------------------------------------------------------------------
__global__ __launch_bounds__(32) void walk_kernel(float* __restrict__ out)
{
    __shared__ float aX1[100], aY1[100], aX2[100], aY2[100], aAR[100];

    const int b = blockIdx.x;
    const int lane = threadIdx.x;
    const unsigned long long* keys = g_keys + b * TK;
    float* ob = out + (size_t)b * NP * 5;

    int npick = 0;
    for (int base = 0; base < TK && npick < 100; base += 32) {
        unsigned long long key = keys[base + lane];
        float sc = __uint_as_float((unsigned)(key >> 32));
        int   idx = 4095 - (int)(key & 0xFFFull);
        if (__shfl_sync(FULLM, sc, 0) <= 0.f) break;
        bool alive = sc > 0.f;

        float bx1 = 0.f, by1 = 0.f, bx2 = 0.f, by2 = 0.f, ba = 0.f;
        if (alive) {
            bx1 = __ldg(&ob[idx * 5 + 0]); by1 = __ldg(&ob[idx * 5 + 1]);
            bx2 = __ldg(&ob[idx * 5 + 2]); by2 = __ldg(&ob[idx * 5 + 3]);
            ba  = fmaxf(bx2 - bx1, 0.f) * fmaxf(by2 - by1, 0.f);
        }

        // test against previously accepted boxes (lane-parallel)
        for (int a = 0; a < npick; a++) {
            float ix1 = fmaxf(aX1[a], bx1);
            float iy1 = fmaxf(aY1[a], by1);
            float ix2 = fminf(aX2[a], bx2);
            float iy2 = fminf(aY2[a], by2);
            float inter = fmaxf(ix2 - ix1, 0.f) * fmaxf(iy2 - iy1, 0.f);
            float iou = inter / (aAR[a] + ba - inter + 1e-9f);
            if (iou > 0.5f) alive = false;
        }

        // intra-chunk pairwise conflicts: conf bit j = "I conflict with lane j"
        unsigned conf = 0;
        #pragma unroll 4
        for (int j = 0; j < 32; j++) {
            float cx1 = __shfl_sync(FULLM, bx1, j);
            float cy1 = __shfl_sync(FULLM, by1, j);
            float cx2 = __shfl_sync(FULLM, bx2, j);
            float cy2 = __shfl_sync(FULLM, by2, j);
            float ca  = __shfl_sync(FULLM, ba,  j);
            float ix1 = fmaxf(cx1, bx1);
            float iy1 = fmaxf(cy1, by1);
            float ix2 = fminf(cx2, bx2);
            float iy2 = fminf(cy2, by2);
            float inter = fmaxf(ix2 - ix1, 0.f) * fmaxf(iy2 - iy1, 0.f);
            float iou = inter / (ca + ba - inter + 1e-9f);
            if (iou > 0.5f) conf |= (1u << j);
        }
        // mycol (on lane k) = mask of lanes that conflict with k
        unsigned mycol = 0;
        #pragma unroll
        for (int j = 0; j < 32; j++) {
            unsigned bcol = __ballot_sync(FULLM, (conf >> j) & 1u);
            if (lane == j) mycol = bcol;
        }

        // scalar resolve, uniform across lanes (no local-mem indexing)
        unsigned alive_mask = __ballot_sync(FULLM, alive);
        unsigned picked = 0;
        const int np0 = npick;
        #pragma unroll 1
        for (int kk = 0; kk < 32; kk++) {
            unsigned kills = __shfl_sync(FULLM, mycol, kk);
            if ((alive_mask >> kk) & 1u) {
                picked |= 1u << kk;
                npick++;
                alive_mask &= ~(kills & (0xFFFFFFFEu << kk));
                if (npick >= 100) break;
            }
        }

        // append accepted boxes + write final score (parallel, popc rank)
        if ((picked >> lane) & 1u) {
            int pos = np0 + __popc(picked & ((1u << lane) - 1u));
            aX1[pos] = bx1; aY1[pos] = by1;
            aX2[pos] = bx2; aY2[pos] = by2;
            aAR[pos] = ba;
            ob[idx * 5 + 4] = sc;
        }
        __syncwarp(FULLM);
    }
}

extern "C" void kernel_launch(void* const* d_in, const int* in_sizes, int n_in,
                              void* d_out, int out_size)
{
    const float* feats     = (const float*)d_in[0];
    const float* proposals = (const float*)d_in[1];
    const float* W_cls     = (const float*)d_in[2];
    const float* b_cls     = (const float*)d_in[3];
    const float* W_box     = (const float*)d_in[4];
    const float* b_box     = (const float*)d_in[5];
    float* out = (float*)d_out;

    head_kernel<<<NROWS / 32, 256>>>(feats, proposals, W_cls, b_cls,
                                     W_box, b_box, out);
    prep_kernel<<<BB, 1024>>>();
    walk_kernel<<<BB, 32>>>(out);
}

// round 7
// speedup vs baseline: 1.1252x; 1.0358x over previous
#include <cuda_runtime.h>

#define BB 16
#define NP 4000
#define TK 1024           // sorted candidate capacity (pow2)
#define KSEL 512          // target top-K for threshold selection
#define DD 1024
#define NROWS (BB*NP)
#define CLIPV 4.135166556742356f   // log(1000/16)
#define FULLM 0xffffffffu

__device__ float g_scores[NROWS];

// ---------------------------------------------------------------------------
// Kernel 1: fused head. DRAM-bound (262 MB feats streamed once).
// 8 warps x 4 rows, double-buffered loads for latency overlap.
// ---------------------------------------------------------------------------
__global__ __launch_bounds__(256, 3) void head_kernel(
    const float* __restrict__ feats, const float* __restrict__ proposals,
    const float* __restrict__ W_cls, const float* __restrict__ b_cls,
    const float* __restrict__ W_box, const float* __restrict__ b_box,
    float* __restrict__ out)
{
    __shared__ float4 wS[6 * 256];   // 6 rows x 1024 floats = 24 KB
    const int tid = threadIdx.x;

    for (int i = tid; i < 6 * 256; i += 256) {
        int c = i >> 8, e = i & 255;
        const float* src = (c < 2) ? (W_cls + c * DD) : (W_box + (c + 2) * DD);
        wS[i] = reinterpret_cast<const float4*>(src)[e];
    }
    __syncthreads();

    const int warp = blockIdx.x * 8 + (tid >> 5);
    const int lane = tid & 31;
    const int row0 = warp * 4;
    if (row0 >= NROWS) return;

    float acc[4][6];
    #pragma unroll
    for (int r = 0; r < 4; r++)
        #pragma unroll
        for (int c = 0; c < 6; c++) acc[r][c] = 0.f;

    const float4* f4 = reinterpret_cast<const float4*>(feats);

    // prologue: load j=0
    float4 fr[4];
    #pragma unroll
    for (int r = 0; r < 4; r++)
        fr[r] = __ldcs(&f4[(row0 + r) * 256 + lane]);

    #pragma unroll
    for (int j = 0; j < 8; j++) {
        float4 nx[4];
        if (j < 7) {
            const int noff = lane + 32 * (j + 1);
            #pragma unroll
            for (int r = 0; r < 4; r++)
                nx[r] = __ldcs(&f4[(row0 + r) * 256 + noff]);
        }
        const int off = lane + 32 * j;
        #pragma unroll
        for (int c = 0; c < 6; c++) {
            float4 w = wS[c * 256 + off];
            #pragma unroll
            for (int r = 0; r < 4; r++)
                acc[r][c] += fr[r].x * w.x + fr[r].y * w.y +
                             fr[r].z * w.z + fr[r].w * w.w;
        }
        if (j < 7) {
            #pragma unroll
            for (int r = 0; r < 4; r++) fr[r] = nx[r];
        }
    }

    #pragma unroll
    for (int r = 0; r < 4; r++)
        #pragma unroll
        for (int c = 0; c < 6; c++)
            #pragma unroll
            for (int s = 16; s > 0; s >>= 1)
                acc[r][c] += __shfl_xor_sync(FULLM, acc[r][c], s);

    if (lane < 4) {
        float v0 = 0.f, v1 = 0.f, v2 = 0.f, v3 = 0.f, v4 = 0.f, v5 = 0.f;
        #pragma unroll
        for (int r = 0; r < 4; r++)
            if (lane == r) {
                v0 = acc[r][0]; v1 = acc[r][1]; v2 = acc[r][2];
                v3 = acc[r][3]; v4 = acc[r][4]; v5 = acc[r][5];
            }
        const int row = row0 + lane;

        float l0 = v0 + b_cls[0];
        float l1 = v1 + b_cls[1];
        float score = 1.f / (1.f + expf(l0 - l1));

        float dx = (v2 + b_box[4]) / 10.0f;
        float dy = (v3 + b_box[5]) / 10.0f;
        float dw = fminf((v4 + b_box[6]) / 5.0f, CLIPV);
        float dh = fminf((v5 + b_box[7]) / 5.0f, CLIPV);

        float4 p = reinterpret_cast<const float4*>(proposals)[row];
        float w  = p.z - p.x;
        float h  = p.w - p.y;
        float cx = p.x + 0.5f * w;
        float cy = p.y + 0.5f * h;
        float pcx = dx * w + cx;
        float pcy = dy * h + cy;
        float pw  = expf(dw) * w;
        float ph  = expf(dh) * h;

        float x1 = fminf(fmaxf(pcx - 0.5f * pw, 0.f), 800.f);
        float y1 = fminf(fmaxf(pcy - 0.5f * ph, 0.f), 800.f);
        float x2 = fminf(fmaxf(pcx + 0.5f * pw, 0.f), 800.f);
        float y2 = fminf(fmaxf(pcy + 0.5f * ph, 0.f), 800.f);

        float* o = out + (size_t)row * 5;
        o[0] = x1; o[1] = y1; o[2] = x2; o[3] = y2;
        o[4] = 0.f;                       // default: not kept
        g_scores[row] = (score > 0.25f) ? score : 0.f;
    }
}

// ---------------------------------------------------------------------------
// Kernel 2: fused NMS — selection + bitonic sort + greedy walk in one kernel.
// One block per batch; keys never leave shared memory.
// ---------------------------------------------------------------------------
__global__ __launch_bounds__(1024) void nms_kernel(float* __restrict__ out)
{
    __shared__ unsigned long long KEY[TK];
    __shared__ int hist[256];
    __shared__ unsigned tbits_s;
    __shared__ int ccount;
    __shared__ float aX1[100], aY1[100], aX2[100], aY2[100], aAR[100];

    const int b = blockIdx.x;
    const int t = threadIdx.x;
    const float* gs = g_scores + b * NP;
    const float4* gs4 = reinterpret_cast<const float4*>(gs);

    if (t < 256) hist[t] = 0;
    if (t == 0) { ccount = 0; tbits_s = 0x3E800000u; }
    __syncthreads();

    // single-pass float4 read: histogram of positive score bits
    float4 sv;
    bool have = t < NP / 4;
    if (have) {
        sv = gs4[t];
        const float* s = &sv.x;
        #pragma unroll
        for (int q = 0; q < 4; q++) {
            float v = s[q];
            if (v > 0.f) {
                unsigned bits = __float_as_uint(v);  // in (0x3E800000, 0x3F800000]
                int bin = min(max((int)((bits - 0x3E800000u) >> 16), 0), 255);
                atomicAdd(&hist[bin], 1);
            }
        }
    }
    __syncthreads();

    // parallel suffix sums over 256 bins (Hillis-Steele)
    for (int off = 1; off < 256; off <<= 1) {
        int v = 0;
        if (t < 256) v = hist[t] + ((t + off < 256) ? hist[t + off] : 0);
        __syncthreads();
        if (t < 256) hist[t] = v;
        __syncthreads();
    }
    if (t < 256) {
        bool ok  = hist[t] >= KSEL;
        bool nxt = (t == 255) ? false : (hist[t + 1] >= KSEL);
        if (ok && !nxt) tbits_s = 0x3E800000u + ((unsigned)t << 16);
    }
    __syncthreads();
    const unsigned tbits = tbits_s;

    // compact candidates (reuse registers, one atomic per thread)
    if (have) {
        const float* s = &sv.x;
        unsigned bits[4];
        int cnt = 0;
        #pragma unroll
        for (int q = 0; q < 4; q++) {
            bits[q] = __float_as_uint(s[q]);
            if (s[q] > 0.f && bits[q] >= tbits) cnt++;
        }
        if (cnt) {
            int slot = atomicAdd(&ccount, cnt);
            #pragma unroll
            for (int q = 0; q < 4; q++) {
                if (s[q] > 0.f && bits[q] >= tbits && slot < TK) {
                    int n = t * 4 + q;
                    KEY[slot++] = ((unsigned long long)bits[q] << 32)
                                | (unsigned long long)(4095 - n);
                }
            }
        }
    }
    __syncthreads();
    const int C = min(ccount, TK);
    if (t >= C) KEY[t] = 0ull;
    __syncthreads();

    // bitonic sort descending, 1024 keys
    {
        unsigned long long e = KEY[t];
        #pragma unroll
        for (int k = 2; k <= 32; k <<= 1)
            #pragma unroll
            for (int j = k >> 1; j > 0; j >>= 1) {
                unsigned long long p = __shfl_xor_sync(FULLM, e, j);
                bool mx = ((t & k) == 0) == ((t & j) == 0);
                e = mx ? (e > p ? e : p) : (e < p ? e : p);
            }
        KEY[t] = e;
    }
    __syncthreads();

    for (int k = 64; k <= TK; k <<= 1) {
        for (int j = k >> 1; j >= 32; j >>= 1) {
            int ixj = t ^ j;
            if (ixj > t) {
                unsigned long long a = KEY[t];
                unsigned long long c = KEY[ixj];
                bool swap = ((t & k) == 0) ? (a < c) : (a > c);
                if (swap) { KEY[t] = c; KEY[ixj] = a; }
            }
            __syncthreads();
        }
        {
            unsigned long long e = KEY[t];
            bool dir = ((t & k) == 0);
            #pragma unroll
            for (int j = 16; j > 0; j >>= 1) {
                unsigned long long p = __shfl_xor_sync(FULLM, e, j);
                bool mx = dir == ((t & j) == 0);
                e = mx ? (e > p ? e : p) : (e < p ? e : p);
            }
            KEY[t] = e;
        }
        __syncthreads();
    }

    // ---- greedy walk (warp 0), keys read straight from smem ----
    if (t < 32) {
        const int lane = t;
        float* ob = out + (size_t)b * NP * 5;
        int npick = 0;
        for (int base = 0; base < TK && npick < 100; base += 32) {
            unsigned long long key = KEY[base + lane];
            float sc = __uint_as_float((unsigned)(key >> 32));
            int   idx = 4095 - (int)(key & 0xFFFull);
            if (__shfl_sync(FULLM, sc, 0) <= 0.f) break;
            bool alive = sc > 0.f;

            float bx1 = 0.f, by1 = 0.f, bx2 = 0.f, by2 = 0.f, ba = 0.f;
            if (alive) {
                bx1 = __ldg(&ob[idx * 5 + 0]); by1 = __ldg(&ob[idx * 5 + 1]);
                bx2 = __ldg(&ob[idx * 5 + 2]); by2 = __ldg(&ob[idx * 5 + 3]);
                ba  = fmaxf(bx2 - bx1, 0.f) * fmaxf(by2 - by1, 0.f);
            }

            // test against previously accepted boxes (lane-parallel)
            for (int a = 0; a < npick; a++) {
                float ix1 = fmaxf(aX1[a], bx1);
                float iy1 = fmaxf(aY1[a], by1);
                float ix2 = fminf(aX2[a], bx2);
                float iy2 = fminf(aY2[a], by2);
                float inter = fmaxf(ix2 - ix1, 0.f) * fmaxf(iy2 - iy1, 0.f);
                float iou = inter / (aAR[a] + ba - inter + 1e-9f);
                if (iou > 0.5f) alive = false;
            }

            // intra-chunk pairwise conflicts
            unsigned conf = 0;
            #pragma unroll 4
            for (int j = 0; j < 32; j++) {
                float cx1 = __shfl_sync(FULLM, bx1, j);
                float cy1 = __shfl_sync(FULLM, by1, j);
                float cx2 = __shfl_sync(FULLM, bx2, j);
                float cy2 = __shfl_sync(FULLM, by2, j);
                float ca  = __shfl_sync(FULLM, ba,  j);
                float ix1 = fmaxf(cx1, bx1);
                float iy1 = fmaxf(cy1, by1);
                float ix2 = fminf(cx2, bx2);
                float iy2 = fminf(cy2, by2);
                float inter = fmaxf(ix2 - ix1, 0.f) * fmaxf(iy2 - iy1, 0.f);
                float iou = inter / (ca + ba - inter + 1e-9f);
                if (iou > 0.5f) conf |= (1u << j);
            }
            unsigned mycol = 0;
            #pragma unroll
            for (int j = 0; j < 32; j++) {
                unsigned bcol = __ballot_sync(FULLM, (conf >> j) & 1u);
                if (lane == j) mycol = bcol;
            }

            // scalar resolve, uniform across lanes
            unsigned alive_mask = __ballot_sync(FULLM, alive);
            unsigned picked = 0;
            const int np0 = npick;
            #pragma unroll 1
            for (int kk = 0; kk < 32; kk++) {
                unsigned kills = __shfl_sync(FULLM, mycol, kk);
                if ((alive_mask >> kk) & 1u) {
                    picked |= 1u << kk;
                    npick++;
                    alive_mask &= ~(kills & (0xFFFFFFFEu << kk));
                    if (npick >= 100) break;
                }
            }

            // append accepted + write final score (parallel, popc rank)
            if ((picked >> lane) & 1u) {
                int pos = np0 + __popc(picked & ((1u << lane) - 1u));
                aX1[pos] = bx1; aY1[pos] = by1;
                aX2[pos] = bx2; aY2[pos] = by2;
                aAR[pos] = ba;
                ob[idx * 5 + 4] = sc;
            }
            __syncwarp(FULLM);
        }
    }
}

extern "C" void kernel_launch(void* const* d_in, const int* in_sizes, int n_in,
                              void* d_out, int out_size)
{
    const float* feats     = (const float*)d_in[0];
    const float* proposals = (const float*)d_in[1];
    const float* W_cls     = (const float*)d_in[2];
    const float* b_cls     = (const float*)d_in[3];
    const float* W_box     = (const float*)d_in[4];
    const float* b_box     = (const float*)d_in[5];
    float* out = (float*)d_out;

    head_kernel<<<NROWS / 32, 256>>>(feats, proposals, W_cls, b_cls,
                                     W_box, b_box, out);
    nms_kernel<<<BB, 1024>>>(out);
}

// round 8
// speedup vs baseline: 1.1287x; 1.0031x over previous
#include <cuda_runtime.h>

#define BB 16
#define NP 4000
#define TK 512            // sorted candidate capacity (pow2)
#define KSEL 384          // target top-K for threshold selection
#define DD 1024
#define NROWS (BB*NP)
#define CLIPV 4.135166556742356f   // log(1000/16)
#define FULLM 0xffffffffu

__device__ float g_scores[NROWS];
__device__ int g_hist[BB * 256];   // zero-init at load; re-zeroed by nms each call

// ---------------------------------------------------------------------------
// Kernel 1: fused head. DRAM-bound (262 MB feats streamed once).
// Also builds the per-batch 256-bin score histogram via global atomics.
// ---------------------------------------------------------------------------
__global__ __launch_bounds__(256, 3) void head_kernel(
    const float* __restrict__ feats, const float* __restrict__ proposals,
    const float* __restrict__ W_cls, const float* __restrict__ b_cls,
    const float* __restrict__ W_box, const float* __restrict__ b_box,
    float* __restrict__ out)
{
    __shared__ float4 wS[6 * 256];   // 6 rows x 1024 floats = 24 KB
    const int tid = threadIdx.x;

    for (int i = tid; i < 6 * 256; i += 256) {
        int c = i >> 8, e = i & 255;
        const float* src = (c < 2) ? (W_cls + c * DD) : (W_box + (c + 2) * DD);
        wS[i] = reinterpret_cast<const float4*>(src)[e];
    }
    __syncthreads();

    const int warp = blockIdx.x * 8 + (tid >> 5);
    const int lane = tid & 31;
    const int row0 = warp * 4;
    if (row0 >= NROWS) return;

    float acc[4][6];
    #pragma unroll
    for (int r = 0; r < 4; r++)
        #pragma unroll
        for (int c = 0; c < 6; c++) acc[r][c] = 0.f;

    const float4* f4 = reinterpret_cast<const float4*>(feats);

    // prologue: load j=0
    float4 fr[4];
    #pragma unroll
    for (int r = 0; r < 4; r++)
        fr[r] = __ldcs(&f4[(row0 + r) * 256 + lane]);

    #pragma unroll
    for (int j = 0; j < 8; j++) {
        float4 nx[4];
        if (j < 7) {
            const int noff = lane + 32 * (j + 1);
            #pragma unroll
            for (int r = 0; r < 4; r++)
                nx[r] = __ldcs(&f4[(row0 + r) * 256 + noff]);
        }
        const int off = lane + 32 * j;
        #pragma unroll
        for (int c = 0; c < 6; c++) {
            float4 w = wS[c * 256 + off];
            #pragma unroll
            for (int r = 0; r < 4; r++)
                acc[r][c] += fr[r].x * w.x + fr[r].y * w.y +
                             fr[r].z * w.z + fr[r].w * w.w;
        }
        if (j < 7) {
            #pragma unroll
            for (int r = 0; r < 4; r++) fr[r] = nx[r];
        }
    }

    #pragma unroll
    for (int r = 0; r < 4; r++)
        #pragma unroll
        for (int c = 0; c < 6; c++)
            #pragma unroll
            for (int s = 16; s > 0; s >>= 1)
                acc[r][c] += __shfl_xor_sync(FULLM, acc[r][c], s);

    if (lane < 4) {
        float v0 = 0.f, v1 = 0.f, v2 = 0.f, v3 = 0.f, v4 = 0.f, v5 = 0.f;
        #pragma unroll
        for (int r = 0; r < 4; r++)
            if (lane == r) {
                v0 = acc[r][0]; v1 = acc[r][1]; v2 = acc[r][2];
                v3 = acc[r][3]; v4 = acc[r][4]; v5 = acc[r][5];
            }
        const int row = row0 + lane;

        float l0 = v0 + b_cls[0];
        float l1 = v1 + b_cls[1];
        float score = 1.f / (1.f + expf(l0 - l1));

        float dx = (v2 + b_box[4]) / 10.0f;
        float dy = (v3 + b_box[5]) / 10.0f;
        float dw = fminf((v4 + b_box[6]) / 5.0f, CLIPV);
        float dh = fminf((v5 + b_box[7]) / 5.0f, CLIPV);

        float4 p = reinterpret_cast<const float4*>(proposals)[row];
        float w  = p.z - p.x;
        float h  = p.w - p.y;
        float cx = p.x + 0.5f * w;
        float cy = p.y + 0.5f * h;
        float pcx = dx * w + cx;
        float pcy = dy * h + cy;
        float pw  = expf(dw) * w;
        float ph  = expf(dh) * h;

        float x1 = fminf(fmaxf(pcx - 0.5f * pw, 0.f), 800.f);
        float y1 = fminf(fmaxf(pcy - 0.5f * ph, 0.f), 800.f);
        float x2 = fminf(fmaxf(pcx + 0.5f * pw, 0.f), 800.f);
        float y2 = fminf(fmaxf(pcy + 0.5f * ph, 0.f), 800.f);

        float* o = out + (size_t)row * 5;
        o[0] = x1; o[1] = y1; o[2] = x2; o[3] = y2;
        o[4] = 0.f;                       // default: not kept

        if (score > 0.25f) {
            g_scores[row] = score;
            unsigned bits = __float_as_uint(score);
            int bin = min(max((int)((bits - 0x3E800000u) >> 16), 0), 255);
            atomicAdd(&g_hist[(row / NP) * 256 + bin], 1);
        } else {
            g_scores[row] = 0.f;
        }
    }
}

// ---------------------------------------------------------------------------
// Kernel 2: fused NMS — threshold (from precomputed hist) + compact +
// bitonic sort + register-resident greedy walk. One block per batch.
// ---------------------------------------------------------------------------
__global__ __launch_bounds__(1024) void nms_kernel(float* __restrict__ out)
{
    __shared__ unsigned long long KEY[TK];
    __shared__ unsigned tbits_s;
    __shared__ int ccount;

    const int b = blockIdx.x;
    const int t = threadIdx.x;
    const float* gs = g_scores + b * NP;
    const float4* gs4 = reinterpret_cast<const float4*>(gs);

    if (t == 0) ccount = 0;

    // ---- threshold from histogram, single warp, suffix scan in registers ----
    if (t < 32) {
        int h[8];
        #pragma unroll
        for (int q = 0; q < 8; q++)
            h[q] = g_hist[b * 256 + t * 8 + q];
        // suffix within lane's 8 bins
        #pragma unroll
        for (int q = 6; q >= 0; q--) h[q] += h[q + 1];
        int lanetot = h[0];
        // inclusive suffix over lanes (sum of lanetot for lanes >= t)
        int suf = lanetot;
        #pragma unroll
        for (int s = 1; s < 32; s <<= 1) {
            int o = __shfl_down_sync(FULLM, suf, s);
            if (t + s < 32) suf += o;
        }
        int excl = suf - lanetot;     // sum over lanes > t
        // S(bin t*8+q) = h[q] + excl; find largest bin with S >= KSEL
        unsigned lm = __ballot_sync(FULLM, (h[0] + excl) >= KSEL);
        if (lm == 0u) {
            if (t == 0) tbits_s = 0x3E800000u;       // keep everything
        } else {
            int hl = 31 - __clz(lm);
            if (t == hl) {
                int bq = 0;
                #pragma unroll
                for (int q = 1; q < 8; q++)
                    if (h[q] + excl >= KSEL) bq = q;
                tbits_s = 0x3E800000u + ((unsigned)(t * 8 + bq) << 16);
            }
        }
    }
    __syncthreads();
    const unsigned tbits = tbits_s;

    // reset histogram for the next launch
    if (t < 256) g_hist[b * 256 + t] = 0;

    // ---- compact candidates (float4 read, one atomic per thread) ----
    if (t < NP / 4) {
        float4 sv = gs4[t];
        const float* s = &sv.x;
        unsigned bits[4];
        int cnt = 0;
        #pragma unroll
        for (int q = 0; q < 4; q++) {
            bits[q] = __float_as_uint(s[q]);
            if (s[q] > 0.f && bits[q] >= tbits) cnt++;
        }
        if (cnt) {
            int slot = atomicAdd(&ccount, cnt);
            #pragma unroll
            for (int q = 0; q < 4; q++) {
                if (s[q] > 0.f && bits[q] >= tbits && slot < TK) {
                    int n = t * 4 + q;
                    KEY[slot++] = ((unsigned long long)bits[q] << 32)
                                | (unsigned long long)(4095 - n);
                }
            }
        }
    }
    __syncthreads();
    const int C = min(ccount, TK);
    if (t >= C && t < TK) KEY[t] = 0ull;
    __syncthreads();

    // ---- bitonic sort descending, 512 keys ----
    if (t < TK) {
        unsigned long long e = KEY[t];
        #pragma unroll
        for (int k = 2; k <= 32; k <<= 1)
            #pragma unroll
            for (int j = k >> 1; j > 0; j >>= 1) {
                unsigned long long p = __shfl_xor_sync(FULLM, e, j);
                bool mx = ((t & k) == 0) == ((t & j) == 0);
                e = mx ? (e > p ? e : p) : (e < p ? e : p);
            }
        KEY[t] = e;
    }
    __syncthreads();

    for (int k = 64; k <= TK; k <<= 1) {
        for (int j = k >> 1; j >= 32; j >>= 1) {
            if (t < TK) {
                int ixj = t ^ j;
                if (ixj > t) {
                    unsigned long long a = KEY[t];
                    unsigned long long c = KEY[ixj];
                    bool swap = ((t & k) == 0) ? (a < c) : (a > c);
                    if (swap) { KEY[t] = c; KEY[ixj] = a; }
                }
            }
            __syncthreads();
        }
        if (t < TK) {
            unsigned long long e = KEY[t];
            bool dir = ((t & k) == 0);
            #pragma unroll
            for (int j = 16; j > 0; j >>= 1) {
                unsigned long long p = __shfl_xor_sync(FULLM, e, j);
                bool mx = dir == ((t & j) == 0);
                e = mx ? (e > p ? e : p) : (e < p ? e : p);
            }
            KEY[t] = e;
        }
        __syncthreads();
    }

    // ---- greedy walk (warp 0), accepted boxes in lane registers ----
    if (t < 32) {
        const int lane = t;
        float* ob = out + (size_t)b * NP * 5;
        float rx1[4], ry1[4], rx2[4], ry2[4], rar[4];
        int npick = 0;
        bool done = false;

        for (int base = 0; base < TK && !done; base += 32) {
            unsigned long long key = KEY[base + lane];
            float sc = __uint_as_float((unsigned)(key >> 32));
            int   idx = 4095 - (int)(key & 0xFFFull);
            if (__shfl_sync(FULLM, sc, 0) <= 0.f) break;

            float bx1 = 0.f, by1 = 0.f, bx2 = 0.f, by2 = 0.f, ba = 0.f;
            if (sc > 0.f) {
                bx1 = __ldg(&ob[idx * 5 + 0]); by1 = __ldg(&ob[idx * 5 + 1]);
                bx2 = __ldg(&ob[idx * 5 + 2]); by2 = __ldg(&ob[idx * 5 + 3]);
                ba  = fmaxf(bx2 - bx1, 0.f) * fmaxf(by2 - by1, 0.f);
            }

            #pragma unroll 1
            for (int kk = 0; kk < 32; kk++) {
                float csc = __shfl_sync(FULLM, sc, kk);
                if (csc <= 0.f) { done = true; break; }
                float cx1 = __shfl_sync(FULLM, bx1, kk);
                float cy1 = __shfl_sync(FULLM, by1, kk);
                float cx2 = __shfl_sync(FULLM, bx2, kk);
                float cy2 = __shfl_sync(FULLM, by2, kk);
                float ca  = __shfl_sync(FULLM, ba,  kk);

                bool conflict = false;
                #pragma unroll
                for (int s2 = 0; s2 < 4; s2++) {
                    if (s2 * 32 + lane < npick) {
                        float ix1 = fmaxf(rx1[s2], cx1);
                        float iy1 = fmaxf(ry1[s2], cy1);
                        float ix2 = fminf(rx2[s2], cx2);
                        float iy2 = fminf(ry2[s2], cy2);
                        float inter = fmaxf(ix2 - ix1, 0.f) *
                                      fmaxf(iy2 - iy1, 0.f);
                        float iou = inter / (rar[s2] + ca - inter + 1e-9f);
                        if (iou > 0.5f) conflict = true;
                    }
                }
                if (__ballot_sync(FULLM, conflict) == 0u) {
                    if (lane == (npick & 31)) {
                        int hi = npick >> 5;
                        if (hi == 0) {
                            rx1[0]=cx1; ry1[0]=cy1; rx2[0]=cx2; ry2[0]=cy2; rar[0]=ca;
                        } else if (hi == 1) {
                            rx1[1]=cx1; ry1[1]=cy1; rx2[1]=cx2; ry2[1]=cy2; rar[1]=ca;
                        } else if (hi == 2) {
                            rx1[2]=cx1; ry1[2]=cy1; rx2[2]=cx2; ry2[2]=cy2; rar[2]=ca;
                        } else {
                            rx1[3]=cx1; ry1[3]=cy1; rx2[3]=cx2; ry2[3]=cy2; rar[3]=ca;
                        }
                    }
                    if (lane == kk) ob[idx * 5 + 4] = sc;
                    npick++;
                    if (npick >= 100) { done = true; break; }
                }
            }
        }
    }
}

extern "C" void kernel_launch(void* const* d_in, const int* in_sizes, int n_in,
                              void* d_out, int out_size)
{
    const float* feats     = (const float*)d_in[0];
    const float* proposals = (const float*)d_in[1];
    const float* W_cls     = (const float*)d_in[2];
    const float* b_cls     = (const float*)d_in[3];
    const float* W_box     = (const float*)d_in[4];
    const float* b_box     = (const float*)d_in[5];
    float* out = (float*)d_out;

    head_kernel<<<NROWS / 32, 256>>>(feats, proposals, W_cls, b_cls,
                                     W_box, b_box, out);
    nms_kernel<<<BB, 1024>>>(out);
}